// round 1
// baseline (speedup 1.0000x reference)
#include <cuda_runtime.h>
#include <cstdint>
#include <cstddef>

#define T_STEPS 1024
#define NENV    256
#define DIM     128
#define FEAT    128
#define GI_COLS 384   // 3*FEAT

// Scratch for precomputed input projections gi = obs @ Wi + bi  : [T*N, 3F]
__device__ float g_gi[(size_t)T_STEPS * NENV * GI_COLS];
// 1 if resets is a 1-byte bool array, 0 if it is int32
__device__ int g_resets_is_bool;

// ---------------------------------------------------------------------------
// Detect resets dtype: if the array were int32 (values 0/1, little-endian),
// every byte at offset % 4 != 0 would be zero. A ~50%-ones bool array has
// nonzero bytes everywhere. Deterministic for fixed input.
// ---------------------------------------------------------------------------
__global__ void detect_resets_kernel(const unsigned char* __restrict__ r) {
    __shared__ int flag;
    if (threadIdx.x == 0) flag = 0;
    __syncthreads();
    int local = 0;
    for (int i = threadIdx.x; i < 4096; i += blockDim.x) {
        if ((i & 3) != 0 && r[i] != 0) local = 1;
    }
    if (local) atomicOr(&flag, 1);
    __syncthreads();
    if (threadIdx.x == 0) g_resets_is_bool = flag;
}

// ---------------------------------------------------------------------------
// Phase 1: gi = obs @ Wi + bi
// A = obs [M=262144, K=128] row-major, B = Wi [128, 384] row-major.
// BM=128, BN=128, BK=16, 256 threads, 8x8 register tile per thread.
// grid = (3, 2048)
// ---------------------------------------------------------------------------
__global__ __launch_bounds__(256)
void gemm_gi_kernel(const float* __restrict__ A,
                    const float* __restrict__ B,
                    const float* __restrict__ bias) {
    __shared__ float As[16][128];
    __shared__ float Bs[16][128];

    const int t  = threadIdx.x;
    const int m0 = blockIdx.y * 128;
    const int n0 = blockIdx.x * 128;
    const int tx = t & 15;          // 0..15 (N direction)
    const int ty = t >> 4;          // 0..15 (M direction)

    float acc[8][8];
    #pragma unroll
    for (int i = 0; i < 8; i++)
        #pragma unroll
        for (int j = 0; j < 8; j++) acc[i][j] = 0.0f;

    for (int k0 = 0; k0 < 128; k0 += 16) {
        // Load A tile (128 rows x 16 k), store transposed As[k][m]
        #pragma unroll
        for (int i = 0; i < 2; i++) {
            int idx = t + i * 256;           // 0..511 float4 slots
            int ar  = idx >> 2;              // row 0..127
            int ac  = (idx & 3) << 2;        // k 0,4,8,12
            float4 v = *reinterpret_cast<const float4*>(
                A + (size_t)(m0 + ar) * 128 + k0 + ac);
            As[ac + 0][ar] = v.x;
            As[ac + 1][ar] = v.y;
            As[ac + 2][ar] = v.z;
            As[ac + 3][ar] = v.w;
        }
        // Load B tile (16 k x 128 n)
        #pragma unroll
        for (int i = 0; i < 2; i++) {
            int idx = t + i * 256;           // 0..511 float4 slots
            int br  = idx >> 5;              // k 0..15
            int bc  = (idx & 31) << 2;       // n 0..124
            float4 v = *reinterpret_cast<const float4*>(
                B + (size_t)(k0 + br) * GI_COLS + n0 + bc);
            *reinterpret_cast<float4*>(&Bs[br][bc]) = v;
        }
        __syncthreads();

        #pragma unroll
        for (int kk = 0; kk < 16; kk++) {
            float a[8], b[8];
            *reinterpret_cast<float4*>(&a[0]) =
                *reinterpret_cast<const float4*>(&As[kk][ty * 8]);
            *reinterpret_cast<float4*>(&a[4]) =
                *reinterpret_cast<const float4*>(&As[kk][ty * 8 + 4]);
            *reinterpret_cast<float4*>(&b[0]) =
                *reinterpret_cast<const float4*>(&Bs[kk][tx * 8]);
            *reinterpret_cast<float4*>(&b[4]) =
                *reinterpret_cast<const float4*>(&Bs[kk][tx * 8 + 4]);
            #pragma unroll
            for (int i = 0; i < 8; i++)
                #pragma unroll
                for (int j = 0; j < 8; j++)
                    acc[i][j] = fmaf(a[i], b[j], acc[i][j]);
        }
        __syncthreads();
    }

    // Epilogue: add bias, store
    #pragma unroll
    for (int i = 0; i < 8; i++) {
        int row = m0 + ty * 8 + i;
        float* Cp = g_gi + (size_t)row * GI_COLS + n0 + tx * 8;
        #pragma unroll
        for (int j = 0; j < 8; j += 4) {
            float4 v;
            v.x = acc[i][j + 0] + bias[n0 + tx * 8 + j + 0];
            v.y = acc[i][j + 1] + bias[n0 + tx * 8 + j + 1];
            v.z = acc[i][j + 2] + bias[n0 + tx * 8 + j + 2];
            v.w = acc[i][j + 3] + bias[n0 + tx * 8 + j + 3];
            *reinterpret_cast<float4*>(Cp + j) = v;
        }
    }
}

// ---------------------------------------------------------------------------
// Phase 2: sequential GRU scan. 128 CTAs x 512 threads, 2 envs per CTA.
// Thread (f = tid&127, kg = tid>>7): holds W[k0..k0+31][f] for all 3 hidden
// matrices in registers (96 regs). h kept in SMEM (reset pre-applied).
// ---------------------------------------------------------------------------
__global__ __launch_bounds__(512, 1)
void gru_scan_kernel(const float* __restrict__ hidden0,
                     const unsigned char* __restrict__ resets_raw,
                     const float* __restrict__ Whr,
                     const float* __restrict__ Whz,
                     const float* __restrict__ Whn,
                     const float* __restrict__ bhn,
                     float* __restrict__ out_final,
                     float* __restrict__ out_ys) {
    __shared__ __align__(16) float hsm[2][FEAT];
    __shared__ float part[2][3][4][FEAT];   // [env][gate][kgroup][f]

    const int tid = threadIdx.x;
    const int f   = tid & 127;
    const int kg  = tid >> 7;       // 0..3
    const int k0  = kg * 32;
    const int envBase = blockIdx.x * 2;

    const bool bmode = (g_resets_is_bool != 0);
    const int* resets_i = reinterpret_cast<const int*>(resets_raw);

    // Load hidden-weight slices into registers
    float wr[32], wz[32], wn[32];
    #pragma unroll
    for (int j = 0; j < 32; j++) {
        int k = k0 + j;
        wr[j] = Whr[k * FEAT + f];
        wz[j] = Whz[k * FEAT + f];
        wn[j] = Whn[k * FEAT + f];
    }
    const float bn = bhn[f];

    // Init h with step-0 reset pre-applied
    if (kg < 2) {
        int e   = kg;
        int env = envBase + e;
        bool d0 = bmode ? (resets_raw[env] != 0) : (resets_i[env] != 0);
        float h0 = hidden0[env * FEAT + f];
        hsm[e][f] = d0 ? 0.0f : h0;
    }
    __syncthreads();

    float finalh = 0.0f;

    for (int t = 0; t < T_STEPS; t++) {
        // Prefetch gi + next-step reset flag (finalize threads only);
        // these global loads overlap the FMA phase.
        float gr = 0.f, gz = 0.f, gn = 0.f;
        bool nextdone = false;
        if (kg < 2) {
            int e = kg, env = envBase + e;
            const float* gp = g_gi + (size_t)(t * NENV + env) * GI_COLS;
            gr = gp[f];
            gz = gp[FEAT + f];
            gn = gp[2 * FEAT + f];
            if (t + 1 < T_STEPS) {
                int ri = (t + 1) * NENV + env;
                nextdone = bmode ? (resets_raw[ri] != 0) : (resets_i[ri] != 0);
            }
        }

        // Matvec partial sums for both envs (weights shared)
        #pragma unroll
        for (int e = 0; e < 2; e++) {
            float ar = 0.f, az = 0.f, an = 0.f;
            #pragma unroll
            for (int j = 0; j < 32; j += 4) {
                const float4 hv =
                    *reinterpret_cast<const float4*>(&hsm[e][k0 + j]);
                ar = fmaf(hv.x, wr[j + 0], ar);
                az = fmaf(hv.x, wz[j + 0], az);
                an = fmaf(hv.x, wn[j + 0], an);
                ar = fmaf(hv.y, wr[j + 1], ar);
                az = fmaf(hv.y, wz[j + 1], az);
                an = fmaf(hv.y, wn[j + 1], an);
                ar = fmaf(hv.z, wr[j + 2], ar);
                az = fmaf(hv.z, wz[j + 2], az);
                an = fmaf(hv.z, wn[j + 2], an);
                ar = fmaf(hv.w, wr[j + 3], ar);
                az = fmaf(hv.w, wz[j + 3], az);
                an = fmaf(hv.w, wn[j + 3], an);
            }
            part[e][0][kg][f] = ar;
            part[e][1][kg][f] = az;
            part[e][2][kg][f] = an;
        }
        __syncthreads();

        // Finalize: kg==0 -> env0, kg==1 -> env1
        if (kg < 2) {
            int e = kg, env = envBase + e;
            float sr = part[e][0][0][f] + part[e][0][1][f] +
                       part[e][0][2][f] + part[e][0][3][f];
            float sz = part[e][1][0][f] + part[e][1][1][f] +
                       part[e][1][2][f] + part[e][1][3][f];
            float sn = part[e][2][0][f] + part[e][2][1][f] +
                       part[e][2][2][f] + part[e][2][3][f];
            float r = 1.0f / (1.0f + __expf(-(gr + sr)));
            float z = 1.0f / (1.0f + __expf(-(gz + sz)));
            float n = tanhf(gn + r * (sn + bn));
            float hold = hsm[e][f];
            float hnew = (1.0f - z) * n + z * hold;
            out_ys[(size_t)(t * NENV + env) * FEAT + f] = hnew;
            hsm[e][f] = nextdone ? 0.0f : hnew;   // pre-apply next reset
            if (t == T_STEPS - 1) finalh = hnew;
        }
        __syncthreads();
    }

    if (kg < 2) {
        int env = envBase + kg;
        out_final[env * FEAT + f] = finalh;
    }
}

// ---------------------------------------------------------------------------
// Launch
// Inputs: 0 hidden_state [N,F], 1 obs [T,N,D], 2 resets [T,N] (bool/int32),
//         3 Wi [D,3F], 4 bi [3F], 5 Whr, 6 Whz, 7 Whn [F,F], 8 bhn [F]
// Output: final_h [N,F] followed by ys [T,N,F]
// ---------------------------------------------------------------------------
extern "C" void kernel_launch(void* const* d_in, const int* in_sizes, int n_in,
                              void* d_out, int out_size) {
    const float*         hidden = (const float*)d_in[0];
    const float*         obs    = (const float*)d_in[1];
    const unsigned char* resets = (const unsigned char*)d_in[2];
    const float*         Wi     = (const float*)d_in[3];
    const float*         bi     = (const float*)d_in[4];
    const float*         Whr    = (const float*)d_in[5];
    const float*         Whz    = (const float*)d_in[6];
    const float*         Whn    = (const float*)d_in[7];
    const float*         bhn    = (const float*)d_in[8];

    float* out       = (float*)d_out;
    float* out_final = out;                       // [N*F]
    float* out_ys    = out + NENV * FEAT;         // [T*N*F]

    detect_resets_kernel<<<1, 256>>>(resets);

    dim3 ggrid(GI_COLS / 128, (T_STEPS * NENV) / 128);   // (3, 2048)
    gemm_gi_kernel<<<ggrid, 256>>>(obs, Wi, bi);

    gru_scan_kernel<<<NENV / 2, 512>>>(hidden, resets, Whr, Whz, Whn, bhn,
                                       out_final, out_ys);
}

// round 2
// speedup vs baseline: 1.5857x; 1.5857x over previous
#include <cuda_runtime.h>
#include <cstdint>
#include <cstddef>

#define T_STEPS 1024
#define NENV    256
#define DIM     128
#define FEAT    128
#define GI_COLS 384   // 3*FEAT

typedef unsigned long long ull;

// Scratch for precomputed input projections gi = obs @ Wi + bi  : [T*N, 3F]
__device__ float g_gi[(size_t)T_STEPS * NENV * GI_COLS];

// ---- packed f32x2 helpers ------------------------------------------------
#define FMA2(d, a, b, c) \
    asm("fma.rn.f32x2 %0, %1, %2, %3;" : "=l"(d) : "l"(a), "l"(b), "l"(c))

__device__ __forceinline__ ull pack2(float lo, float hi) {
    ull r;
    asm("mov.b64 %0, {%1, %2};" : "=l"(r)
        : "r"(__float_as_uint(lo)), "r"(__float_as_uint(hi)));
    return r;
}
__device__ __forceinline__ void unpack2(float& lo, float& hi, ull v) {
    unsigned a, b;
    asm("mov.b64 {%0, %1}, %2;" : "=r"(a), "=r"(b) : "l"(v));
    lo = __uint_as_float(a);
    hi = __uint_as_float(b);
}

// ---------------------------------------------------------------------------
// Phase 1: gi = obs @ Wi + bi     (M=262144, N=384, K=128)
// BM=128, BN=128, BK=16, 256 threads. 8(m)x8(n) tile per thread, m packed
// into 4 f32x2 accumulator rows. grid = (3, 2048).
// ---------------------------------------------------------------------------
__global__ __launch_bounds__(256)
void gemm_gi_kernel(const float* __restrict__ A,
                    const float* __restrict__ B,
                    const float* __restrict__ bias) {
    __shared__ __align__(16) float As[16][128];
    __shared__ __align__(16) float Bs[16][128];

    const int t  = threadIdx.x;
    const int m0 = blockIdx.y * 128;
    const int n0 = blockIdx.x * 128;
    const int tx = t & 15;          // N direction
    const int ty = t >> 4;          // M direction

    ull acc2[4][8];                 // [m-pair][n] ; lanes = rows 2i, 2i+1
    #pragma unroll
    for (int i = 0; i < 4; i++)
        #pragma unroll
        for (int j = 0; j < 8; j++) acc2[i][j] = 0ull;

    for (int k0 = 0; k0 < 128; k0 += 16) {
        // Load A tile (128 m x 16 k), transposed into As[k][m]
        #pragma unroll
        for (int i = 0; i < 2; i++) {
            int idx = t + i * 256;
            int ar  = idx >> 2;
            int ac  = (idx & 3) << 2;
            float4 v = *reinterpret_cast<const float4*>(
                A + (size_t)(m0 + ar) * 128 + k0 + ac);
            As[ac + 0][ar] = v.x;
            As[ac + 1][ar] = v.y;
            As[ac + 2][ar] = v.z;
            As[ac + 3][ar] = v.w;
        }
        // Load B tile (16 k x 128 n)
        #pragma unroll
        for (int i = 0; i < 2; i++) {
            int idx = t + i * 256;
            int br  = idx >> 5;
            int bc  = (idx & 31) << 2;
            float4 v = *reinterpret_cast<const float4*>(
                B + (size_t)(k0 + br) * GI_COLS + n0 + bc);
            *reinterpret_cast<float4*>(&Bs[br][bc]) = v;
        }
        __syncthreads();

        #pragma unroll
        for (int kk = 0; kk < 16; kk++) {
            const ull* ap = reinterpret_cast<const ull*>(&As[kk][ty * 8]);
            ull a0 = ap[0], a1 = ap[1], a2 = ap[2], a3 = ap[3];
            float4 bA = *reinterpret_cast<const float4*>(&Bs[kk][tx * 8]);
            float4 bB = *reinterpret_cast<const float4*>(&Bs[kk][tx * 8 + 4]);
            float bv[8] = {bA.x, bA.y, bA.z, bA.w, bB.x, bB.y, bB.z, bB.w};
            #pragma unroll
            for (int j = 0; j < 8; j++) {
                ull bd = pack2(bv[j], bv[j]);
                FMA2(acc2[0][j], a0, bd, acc2[0][j]);
                FMA2(acc2[1][j], a1, bd, acc2[1][j]);
                FMA2(acc2[2][j], a2, bd, acc2[2][j]);
                FMA2(acc2[3][j], a3, bd, acc2[3][j]);
            }
        }
        __syncthreads();
    }

    // Epilogue: add bias, store
    float bb[8];
    #pragma unroll
    for (int j = 0; j < 8; j++) bb[j] = bias[n0 + tx * 8 + j];

    #pragma unroll
    for (int ip = 0; ip < 4; ip++) {
        float r0[8], r1[8];
        #pragma unroll
        for (int j = 0; j < 8; j++) {
            float lo, hi;
            unpack2(lo, hi, acc2[ip][j]);
            r0[j] = lo + bb[j];
            r1[j] = hi + bb[j];
        }
        int row0 = m0 + ty * 8 + 2 * ip;
        float* C0 = g_gi + (size_t)row0 * GI_COLS + n0 + tx * 8;
        float* C1 = C0 + GI_COLS;
        *reinterpret_cast<float4*>(C0)     = make_float4(r0[0], r0[1], r0[2], r0[3]);
        *reinterpret_cast<float4*>(C0 + 4) = make_float4(r0[4], r0[5], r0[6], r0[7]);
        *reinterpret_cast<float4*>(C1)     = make_float4(r1[0], r1[1], r1[2], r1[3]);
        *reinterpret_cast<float4*>(C1 + 4) = make_float4(r1[4], r1[5], r1[6], r1[7]);
    }
}

// ---------------------------------------------------------------------------
// Phase 2: sequential GRU scan. 128 CTAs x 512 threads, 2 envs per CTA.
// Thread (f = tid&127, kg = tid>>7): holds W[k0..k0+31][f] for the 3 hidden
// matrices packed as 16 f32x2 k-pairs each (96 regs total). h in SMEM.
// Resets dtype (bool vs int32) detected in-kernel via __syncthreads_or.
// ---------------------------------------------------------------------------
__global__ __launch_bounds__(512, 1)
void gru_scan_kernel(const float* __restrict__ hidden0,
                     const unsigned char* __restrict__ resets_raw,
                     const float* __restrict__ Whr,
                     const float* __restrict__ Whz,
                     const float* __restrict__ Whn,
                     const float* __restrict__ bhn,
                     float* __restrict__ out_final,
                     float* __restrict__ out_ys) {
    __shared__ __align__(16) float hsm[2][FEAT];
    __shared__ float part[2][3][4][FEAT];   // [env][gate][kgroup][f]

    const int tid = threadIdx.x;
    const int f   = tid & 127;
    const int kg  = tid >> 7;       // 0..3
    const int k0  = kg * 32;
    const int envBase = blockIdx.x * 2;

    // Detect resets dtype: int32 0/1 little-endian would have zero bytes at
    // all offsets % 4 != 0; a ~50%-ones bool array does not.
    int local = 0;
    for (int i = tid; i < 4096; i += 512)
        if ((i & 3) != 0 && resets_raw[i] != 0) local = 1;
    const bool bmode = __syncthreads_or(local);
    const int* resets_i = reinterpret_cast<const int*>(resets_raw);

    // Load hidden-weight slices into registers as packed k-pairs
    ull wr2[16], wz2[16], wn2[16];
    #pragma unroll
    for (int j = 0; j < 16; j++) {
        int k = k0 + 2 * j;
        wr2[j] = pack2(Whr[k * FEAT + f], Whr[(k + 1) * FEAT + f]);
        wz2[j] = pack2(Whz[k * FEAT + f], Whz[(k + 1) * FEAT + f]);
        wn2[j] = pack2(Whn[k * FEAT + f], Whn[(k + 1) * FEAT + f]);
    }
    const float bn = bhn[f];

    // Init h with step-0 reset pre-applied
    if (kg < 2) {
        int e   = kg;
        int env = envBase + e;
        bool d0 = bmode ? (resets_raw[env] != 0) : (resets_i[env] != 0);
        float h0 = hidden0[env * FEAT + f];
        hsm[e][f] = d0 ? 0.0f : h0;
    }
    __syncthreads();

    float finalh = 0.0f;

    for (int t = 0; t < T_STEPS; t++) {
        // Prefetch gi + next-step reset flag (finalize threads only)
        float gr = 0.f, gz = 0.f, gn = 0.f;
        bool nextdone = false;
        if (kg < 2) {
            int e = kg, env = envBase + e;
            const float* gp = g_gi + (size_t)(t * NENV + env) * GI_COLS;
            gr = gp[f];
            gz = gp[FEAT + f];
            gn = gp[2 * FEAT + f];
            if (t + 1 < T_STEPS) {
                int ri = (t + 1) * NENV + env;
                nextdone = bmode ? (resets_raw[ri] != 0) : (resets_i[ri] != 0);
            }
        }

        // Packed matvec partial sums for both envs (weights shared)
        #pragma unroll
        for (int e = 0; e < 2; e++) {
            ull ar = 0ull, az = 0ull, an = 0ull;
            const ull* h64 = reinterpret_cast<const ull*>(&hsm[e][k0]);
            #pragma unroll
            for (int j = 0; j < 16; j++) {
                ull h2 = h64[j];
                FMA2(ar, h2, wr2[j], ar);
                FMA2(az, h2, wz2[j], az);
                FMA2(an, h2, wn2[j], an);
            }
            float lo, hi;
            unpack2(lo, hi, ar); part[e][0][kg][f] = lo + hi;
            unpack2(lo, hi, az); part[e][1][kg][f] = lo + hi;
            unpack2(lo, hi, an); part[e][2][kg][f] = lo + hi;
        }
        __syncthreads();

        // Finalize: kg==0 -> env0, kg==1 -> env1
        if (kg < 2) {
            int e = kg, env = envBase + e;
            float sr = part[e][0][0][f] + part[e][0][1][f] +
                       part[e][0][2][f] + part[e][0][3][f];
            float sz = part[e][1][0][f] + part[e][1][1][f] +
                       part[e][1][2][f] + part[e][1][3][f];
            float sn = part[e][2][0][f] + part[e][2][1][f] +
                       part[e][2][2][f] + part[e][2][3][f];
            float r = __fdividef(1.0f, 1.0f + __expf(-(gr + sr)));
            float z = __fdividef(1.0f, 1.0f + __expf(-(gz + sz)));
            float ex = __expf(2.0f * (gn + r * (sn + bn)));
            float n = __fdividef(ex - 1.0f, ex + 1.0f);   // tanh
            float hold = hsm[e][f];
            float hnew = (1.0f - z) * n + z * hold;
            out_ys[(size_t)(t * NENV + env) * FEAT + f] = hnew;
            hsm[e][f] = nextdone ? 0.0f : hnew;   // pre-apply next reset
            if (t == T_STEPS - 1) finalh = hnew;
        }
        __syncthreads();
    }

    if (kg < 2) {
        int env = envBase + kg;
        out_final[env * FEAT + f] = finalh;
    }
}

// ---------------------------------------------------------------------------
// Launch
// Inputs: 0 hidden_state [N,F], 1 obs [T,N,D], 2 resets [T,N] (bool/int32),
//         3 Wi [D,3F], 4 bi [3F], 5 Whr, 6 Whz, 7 Whn [F,F], 8 bhn [F]
// Output: final_h [N,F] followed by ys [T,N,F]
// ---------------------------------------------------------------------------
extern "C" void kernel_launch(void* const* d_in, const int* in_sizes, int n_in,
                              void* d_out, int out_size) {
    const float*         hidden = (const float*)d_in[0];
    const float*         obs    = (const float*)d_in[1];
    const unsigned char* resets = (const unsigned char*)d_in[2];
    const float*         Wi     = (const float*)d_in[3];
    const float*         bi     = (const float*)d_in[4];
    const float*         Whr    = (const float*)d_in[5];
    const float*         Whz    = (const float*)d_in[6];
    const float*         Whn    = (const float*)d_in[7];
    const float*         bhn    = (const float*)d_in[8];

    float* out       = (float*)d_out;
    float* out_final = out;                       // [N*F]
    float* out_ys    = out + NENV * FEAT;         // [T*N*F]

    dim3 ggrid(GI_COLS / 128, (T_STEPS * NENV) / 128);   // (3, 2048)
    gemm_gi_kernel<<<ggrid, 256>>>(obs, Wi, bi);

    gru_scan_kernel<<<NENV / 2, 512>>>(hidden, resets, Whr, Whz, Whn, bhn,
                                       out_final, out_ys);
}